// round 2
// baseline (speedup 1.0000x reference)
#include <cuda_runtime.h>
#include <cstdint>

// Problem constants
#define NB   4
#define CC   64
#define HH   256
#define WW   448
#define HWSZ (HH * WW)            // 114688
#define CP   68                   // 64 ch + 1 norm, padded to 68 for 16B alignment

// Scratch accumulator for ONE batch image, channel-last: [h][w][CP]  (~31.2 MB)
// Zero-initialized at module load; every kernel_launch leaves it zeroed again
// (norm_zero_kernel stores 0 after reading), so graph replays are deterministic.
__device__ float g_accum[(size_t)HWSZ * CP];

// ---------------------------------------------------------------------------
// Splat one batch image. One block = 32 consecutive pixels (same h row).
// 256 threads. Coalesced NCHW input reads staged through smem, then
// vector red.global.add.v4.f32 into the (L2-resident) channel-last accumulator.
// ---------------------------------------------------------------------------
__global__ __launch_bounds__(256) void splat_kernel(
    const float* __restrict__ inp,      // [CC][HWSZ] for this batch
    const float* __restrict__ flow,     // [2][HWSZ]
    const float* __restrict__ metric)   // [HWSZ]
{
    __shared__ float s_in[32][33];     // 32 channels x 32 pixels (+pad)
    __shared__ int   s_base[32][4];    // accum base offset per corner
    __shared__ float s_wgt[32][4];     // bilinear weight per corner (0 if invalid)
    __shared__ float s_m[32];          // exp(metric)

    const int tid = threadIdx.x;
    const int p0  = blockIdx.x * 32;   // W%32==0 -> block never straddles a row

    if (tid < 32) {
        int rem = p0 + tid;
        int h   = rem / WW;
        int w   = rem - h * WW;

        float fx = flow[rem];
        float fy = flow[HWSZ + rem];
        float m  = expf(metric[rem]);

        float xx  = (float)w + fx;
        float yy  = (float)h + fy;
        float x0f = floorf(xx);
        float y0f = floorf(yy);
        int x0 = (int)x0f;
        int y0 = (int)y0f;
        float ax = xx - x0f;
        float ay = yy - y0f;

        float wgt[4];
        wgt[0] = (1.f - ax) * (1.f - ay);  // (x0, y0)
        wgt[1] = ax * (1.f - ay);          // (x1, y0)
        wgt[2] = (1.f - ax) * ay;          // (x0, y1)
        wgt[3] = ax * ay;                  // (x1, y1)

        #pragma unroll
        for (int j = 0; j < 4; j++) {
            int xi = x0 + (j & 1);
            int yi = y0 + (j >> 1);
            bool valid = ((unsigned)xi < (unsigned)WW) && ((unsigned)yi < (unsigned)HH);
            s_base[tid][j] = valid ? (yi * WW + xi) * CP : 0;
            s_wgt[tid][j]  = valid ? wgt[j] : 0.f;
        }
        s_m[tid] = m;
    }
    __syncthreads();

    const int lane = tid & 31;
    const int wa   = tid >> 5;         // 8 warps

    const float* ibase = inp + p0;
    const float m = s_m[lane];

    #pragma unroll
    for (int c0 = 0; c0 < CC; c0 += 32) {
        // Stage 32 channels x 32 pixels, coalesced (lanes across w)
        #pragma unroll
        for (int k = 0; k < 4; k++) {
            int cr = wa + k * 8;       // 0..31
            s_in[cr][lane] = ibase[(size_t)(c0 + cr) * HWSZ + lane];
        }
        __syncthreads();

        // This thread: pixel = lane, channels c0 + wa*4 .. +3
        float4 v;
        v.x = s_in[wa * 4 + 0][lane] * m;
        v.y = s_in[wa * 4 + 1][lane] * m;
        v.z = s_in[wa * 4 + 2][lane] * m;
        v.w = s_in[wa * 4 + 3][lane] * m;

        #pragma unroll
        for (int j = 0; j < 4; j++) {
            float wg = s_wgt[lane][j];
            if (wg != 0.f) {
                float* addr = g_accum + s_base[lane][j] + c0 + wa * 4;
                asm volatile(
                    "red.global.add.v4.f32 [%0], {%1, %2, %3, %4};"
                    :: "l"(addr), "f"(v.x * wg), "f"(v.y * wg),
                       "f"(v.z * wg), "f"(v.w * wg)
                    : "memory");
            }
        }
        __syncthreads();
    }

    // Norm channel (index 64), one lane per pixel
    if (tid < 32) {
        float mm = s_m[tid];
        #pragma unroll
        for (int j = 0; j < 4; j++) {
            float wg = s_wgt[tid][j];
            if (wg != 0.f) {
                atomicAdd(g_accum + s_base[tid][j] + 64, mm * wg);
            }
        }
    }
}

// ---------------------------------------------------------------------------
// Normalize one batch image AND re-zero the accumulator behind itself.
// One block = 32 pixels: stage accum through smem (coalesced L2 reads),
// store zeros back (lines resident -> cheap), write NCHW output coalesced.
// ---------------------------------------------------------------------------
__global__ __launch_bounds__(256) void norm_zero_kernel(
    float* __restrict__ out)            // [CC][HWSZ] for this batch
{
    __shared__ float s_acc[32 * CP];   // 8704 B

    const int tid = threadIdx.x;
    const int p0  = blockIdx.x * 32;

    float* abase = g_accum + (size_t)p0 * CP;
    #pragma unroll
    for (int i = tid; i < 32 * CP; i += 256) {
        s_acc[i] = abase[i];
        abase[i] = 0.f;                // re-zero for next batch / next replay
    }
    __syncthreads();

    const int lane = tid & 31;
    const int wa   = tid >> 5;

    float* obase = out + p0;

    float nm  = s_acc[lane * CP + 64];
    float inv = (nm == 0.f) ? 1.f : (1.f / nm);

    #pragma unroll
    for (int k = 0; k < 8; k++) {
        int c = wa + k * 8;
        obase[(size_t)c * HWSZ + lane] = s_acc[lane * CP + c] * inv;
    }
}

// ---------------------------------------------------------------------------
extern "C" void kernel_launch(void* const* d_in, const int* in_sizes, int n_in,
                              void* d_out, int out_size)
{
    const float* inp    = (const float*)d_in[0];
    const float* flow   = (const float*)d_in[1];
    const float* metric = (const float*)d_in[2];
    float* out = (float*)d_out;

    const int nblk = HWSZ / 32;        // 3584

    for (int n = 0; n < NB; n++) {
        splat_kernel<<<nblk, 256>>>(
            inp    + (size_t)n * CC * HWSZ,
            flow   + (size_t)n * 2  * HWSZ,
            metric + (size_t)n * HWSZ);
        norm_zero_kernel<<<nblk, 256>>>(
            out    + (size_t)n * CC * HWSZ);
    }
}

// round 3
// speedup vs baseline: 1.0442x; 1.0442x over previous
#include <cuda_runtime.h>
#include <cstdint>

// Problem constants
#define NB   4
#define CC   64
#define HH   256
#define WW   448
#define HWSZ (HH * WW)            // 114688
#define CP   68                   // 64 ch + 1 norm, padded to 68 for 16B alignment

// Scratch accumulator for ONE batch image, channel-last: [h][w][CP]  (~31.2 MB)
// Zero-initialized at module load; every kernel_launch leaves it zeroed again
// (norm_zero_kernel stores 0 after reading), so graph replays are deterministic.
__device__ float g_accum[(size_t)HWSZ * CP];

// ---------------------------------------------------------------------------
// Splat one batch image. One block = 32 consecutive pixels (same h row).
// 256 threads. Input read with streaming hint (__ldcs) so the 29 MB stream
// doesn't evict the L2-resident accumulator. Vector red.global.add.v4.f32.
// ---------------------------------------------------------------------------
__global__ __launch_bounds__(256) void splat_kernel(
    const float* __restrict__ inp,      // [CC][HWSZ] for this batch
    const float* __restrict__ flow,     // [2][HWSZ]
    const float* __restrict__ metric)   // [HWSZ]
{
    __shared__ float s_in[32][33];     // 32 channels x 32 pixels (+pad)
    __shared__ int   s_base[32][4];    // accum base offset per corner
    __shared__ float s_wgt[32][4];     // bilinear weight per corner (0 if invalid)
    __shared__ float s_m[32];          // exp(metric)

    const int tid = threadIdx.x;
    const int p0  = blockIdx.x * 32;   // W%32==0 -> block never straddles a row

    if (tid < 32) {
        int rem = p0 + tid;
        int h   = rem / WW;
        int w   = rem - h * WW;

        float fx = __ldcs(flow + rem);
        float fy = __ldcs(flow + HWSZ + rem);
        float m  = expf(__ldcs(metric + rem));

        float xx  = (float)w + fx;
        float yy  = (float)h + fy;
        float x0f = floorf(xx);
        float y0f = floorf(yy);
        int x0 = (int)x0f;
        int y0 = (int)y0f;
        float ax = xx - x0f;
        float ay = yy - y0f;

        float wgt[4];
        wgt[0] = (1.f - ax) * (1.f - ay);  // (x0, y0)
        wgt[1] = ax * (1.f - ay);          // (x1, y0)
        wgt[2] = (1.f - ax) * ay;          // (x0, y1)
        wgt[3] = ax * ay;                  // (x1, y1)

        #pragma unroll
        for (int j = 0; j < 4; j++) {
            int xi = x0 + (j & 1);
            int yi = y0 + (j >> 1);
            bool valid = ((unsigned)xi < (unsigned)WW) && ((unsigned)yi < (unsigned)HH);
            s_base[tid][j] = valid ? (yi * WW + xi) * CP : 0;
            s_wgt[tid][j]  = valid ? wgt[j] : 0.f;
        }
        s_m[tid] = m;
    }
    __syncthreads();

    const int lane = tid & 31;
    const int wa   = tid >> 5;         // 8 warps

    const float* ibase = inp + p0;
    const float m = s_m[lane];

    #pragma unroll
    for (int c0 = 0; c0 < CC; c0 += 32) {
        // Stage 32 channels x 32 pixels, coalesced, streaming (evict-first)
        #pragma unroll
        for (int k = 0; k < 4; k++) {
            int cr = wa + k * 8;       // 0..31
            s_in[cr][lane] = __ldcs(ibase + (size_t)(c0 + cr) * HWSZ + lane);
        }
        __syncthreads();

        // This thread: pixel = lane, channels c0 + wa*4 .. +3
        float4 v;
        v.x = s_in[wa * 4 + 0][lane] * m;
        v.y = s_in[wa * 4 + 1][lane] * m;
        v.z = s_in[wa * 4 + 2][lane] * m;
        v.w = s_in[wa * 4 + 3][lane] * m;

        #pragma unroll
        for (int j = 0; j < 4; j++) {
            float wg = s_wgt[lane][j];
            if (wg != 0.f) {
                float* addr = g_accum + s_base[lane][j] + c0 + wa * 4;
                asm volatile(
                    "red.global.add.v4.f32 [%0], {%1, %2, %3, %4};"
                    :: "l"(addr), "f"(v.x * wg), "f"(v.y * wg),
                       "f"(v.z * wg), "f"(v.w * wg)
                    : "memory");
            }
        }
        __syncthreads();
    }

    // Norm channel (index 64), one lane per pixel
    if (tid < 32) {
        float mm = s_m[tid];
        #pragma unroll
        for (int j = 0; j < 4; j++) {
            float wg = s_wgt[tid][j];
            if (wg != 0.f) {
                atomicAdd(g_accum + s_base[tid][j] + 64, mm * wg);
            }
        }
    }
}

// ---------------------------------------------------------------------------
// Normalize one batch image AND re-zero the accumulator behind itself.
// One block = 64 pixels: stage accum through smem with float4 loads
// (17 float4 per pixel), zero-store float4 back, write NCHW output with
// streaming stores (evict-first; output is never re-read).
// ---------------------------------------------------------------------------
__global__ __launch_bounds__(256) void norm_zero_kernel(
    float* __restrict__ out)            // [CC][HWSZ] for this batch
{
    __shared__ float4 s4[64 * 17];     // 64 px x 68 floats = 17408 B

    const int tid = threadIdx.x;
    const int p0  = blockIdx.x * 64;

    float4* abase = reinterpret_cast<float4*>(g_accum + (size_t)p0 * CP);
    const float4 z = make_float4(0.f, 0.f, 0.f, 0.f);

    // 64*17 = 1088 float4: 4 full strides of 256 + tail of 64
    #pragma unroll
    for (int k = 0; k < 4; k++) {
        int i = tid + k * 256;
        s4[i] = abase[i];
        abase[i] = z;                  // re-zero for next batch / next replay
    }
    if (tid < 64) {
        int i = tid + 1024;
        s4[i] = abase[i];
        abase[i] = z;
    }
    __syncthreads();

    const float* s = reinterpret_cast<const float*>(s4);
    const int lane = tid & 31;
    const int wa   = tid >> 5;

    const int pix   = lane + 32 * (wa & 1);   // 0..63
    const int cbase = wa >> 1;                // 0..3

    float nm  = s[pix * CP + 64];
    float inv = (nm == 0.f) ? 1.f : (1.f / nm);

    float* obase = out + p0 + pix;
    #pragma unroll
    for (int k = 0; k < 16; k++) {
        int c = cbase + 4 * k;                // covers 0..63
        __stcs(obase + (size_t)c * HWSZ, s[pix * CP + c] * inv);
    }
}

// ---------------------------------------------------------------------------
extern "C" void kernel_launch(void* const* d_in, const int* in_sizes, int n_in,
                              void* d_out, int out_size)
{
    const float* inp    = (const float*)d_in[0];
    const float* flow   = (const float*)d_in[1];
    const float* metric = (const float*)d_in[2];
    float* out = (float*)d_out;

    for (int n = 0; n < NB; n++) {
        splat_kernel<<<HWSZ / 32, 256>>>(
            inp    + (size_t)n * CC * HWSZ,
            flow   + (size_t)n * 2  * HWSZ,
            metric + (size_t)n * HWSZ);
        norm_zero_kernel<<<HWSZ / 64, 256>>>(
            out    + (size_t)n * CC * HWSZ);
    }
}